// round 13
// baseline (speedup 1.0000x reference)
#include <cuda_runtime.h>
#include <cuda_bf16.h>
#include <cstdint>

// Problem constants
#define N_MET   100000
#define N_RXN   50000
#define E_SUB   2000000
#define E_ALL   4000000
#define MSG_DIM 16
#define HIDDEN  32

// Persistent scratch: per-reaction accumulated messages [N_RXN][16]
__device__ float g_hrxn[N_RXN * MSG_DIM];

// Edge-MLP weights in constant memory (filled by async D2D copies each launch).
// cW2p: W2m [32][16] row-major reinterpreted as 8 packed f32-pairs per row.
// (R6 configuration — measured best at 50.5us.)
__constant__ unsigned long long cW2p[HIDDEN * (MSG_DIM / 2)];
__constant__ float cW1[2 * HIDDEN];   // row 0: x-weights, row 1: s-weights
__constant__ float cB1[HIDDEN];
__constant__ float cB2[MSG_DIM];

// ---------------------------------------------------------------------------
// helpers
// ---------------------------------------------------------------------------
__device__ __forceinline__ unsigned long long pack2(float a, float b) {
    unsigned long long r;
    asm("mov.b64 %0, {%1,%2};" : "=l"(r) : "f"(a), "f"(b));
    return r;
}
__device__ __forceinline__ unsigned long long fma2(unsigned long long a,
                                                   unsigned long long b,
                                                   unsigned long long c) {
    unsigned long long d;
    asm("fma.rn.f32x2 %0, %1, %2, %3;" : "=l"(d) : "l"(a), "l"(b), "l"(c));
    return d;
}
__device__ __forceinline__ float2 unpack2(unsigned long long a) {
    float2 f;
    asm("mov.b64 {%0,%1}, %2;" : "=f"(f.x), "=f"(f.y) : "l"(a));
    return f;
}
__device__ __forceinline__ float fast_ex2(float x) {
    float y; asm("ex2.approx.ftz.f32 %0, %1;" : "=f"(y) : "f"(x)); return y;
}
__device__ __forceinline__ float fast_rcp(float x) {
    float y; asm("rcp.approx.ftz.f32 %0, %1;" : "=f"(y) : "f"(x)); return y;
}
// single-MUFU tanh (MUFU.TANH) — edge kernel (measured: no precision impact)
__device__ __forceinline__ float tanh_fast(float x) {
    float y; asm("tanh.approx.f32 %0, %1;" : "=f"(y) : "f"(x)); return y;
}
// accurate tanh via ex2+rcp (input pre-scaled by 2*log2(e)) — rate kernel
__device__ __forceinline__ float tanh_from_scaled(float u_scaled) {
    float e = fast_ex2(u_scaled);
    float r = fast_rcp(e + 1.0f);
    return fmaf(-2.0f, r, 1.0f);
}
__device__ __forceinline__ void prefetch_l2(const void* p) {
    asm volatile("prefetch.global.L2 [%0];" :: "l"(p));
}

__device__ __forceinline__ void red_add_v4(float* p, float a, float b, float c, float d) {
    asm volatile("red.global.add.v4.f32 [%0], {%1,%2,%3,%4};"
                 :: "l"(p), "f"(a), "f"(b), "f"(c), "f"(d) : "memory");
}
__device__ __forceinline__ void red_add_f32(float* p, float a) {
    asm volatile("red.global.add.f32 [%0], %1;" :: "l"(p), "f"(a) : "memory");
}

// ---------------------------------------------------------------------------
// Kernel 0: standalone L2 prefetch of dxdt's 48MB streams. Fire-and-forget:
// the kernel exits once requests are issued; DRAM->L2 fills overlap the
// memsets and the front of the edge kernel (before its L2 pressure ramps).
// ---------------------------------------------------------------------------
#define LINES_PER_ARRAY (E_ALL * 4 / 128)   // 131072 lines of 128B per 16MB array
#define PF_TPB 512

__global__ __launch_bounds__(PF_TPB)
void prefetch_kernel(const float* __restrict__ sto_all,
                     const int*   __restrict__ rxn_all,
                     const int*   __restrict__ met_all) {
    int li = blockIdx.x * PF_TPB + threadIdx.x;
    if (li < LINES_PER_ARRAY) {
        prefetch_l2(reinterpret_cast<const char*>(sto_all) + (size_t)li * 128);
    } else if (li < 2 * LINES_PER_ARRAY) {
        prefetch_l2(reinterpret_cast<const char*>(rxn_all) + (size_t)(li - LINES_PER_ARRAY) * 128);
    } else if (li < 3 * LINES_PER_ARRAY) {
        prefetch_l2(reinterpret_cast<const char*>(met_all) + (size_t)(li - 2 * LINES_PER_ARRAY) * 128);
    }
}

// ---------------------------------------------------------------------------
// Kernel 1: per-edge message MLP + scatter-add into g_hrxn  (exact R6 config,
// measured 50.5us: 4 edges/thread, quad-amortized constant weight reads)
//   msg = tanh([x,s] @ W1m + b1m) @ W2m + b2m      (2->32->16)
// ---------------------------------------------------------------------------
#define K1_TPB 128
#define K1_EPT 4

__global__ __launch_bounds__(K1_TPB)
void edge_msg_kernel(const float* __restrict__ x_met,
                     const float* __restrict__ sto_sub,
                     const int*   __restrict__ met_sub,
                     const int*   __restrict__ rxn_sub) {
    const int tid4 = blockIdx.x * K1_TPB + threadIdx.x;   // quad index
    if (tid4 * K1_EPT >= E_SUB) return;                   // E_SUB % 4 == 0

    // 3 vector stream loads (LDG.128) + 4 gathers, front-batched
    int4   mi = __ldcs(reinterpret_cast<const int4*>(met_sub) + tid4);
    float4 sv = __ldcs(reinterpret_cast<const float4*>(sto_sub) + tid4);
    int4   ri = __ldcs(reinterpret_cast<const int4*>(rxn_sub) + tid4);

    float x[K1_EPT], s[K1_EPT];
    x[0] = __ldg(x_met + mi.x); x[1] = __ldg(x_met + mi.y);
    x[2] = __ldg(x_met + mi.z); x[3] = __ldg(x_met + mi.w);
    s[0] = sv.x; s[1] = sv.y; s[2] = sv.z; s[3] = sv.w;

    // accumulators init = b2m   (4 edges x 8 u64)
    unsigned long long acc[K1_EPT][MSG_DIM / 2];
    #pragma unroll
    for (int q = 0; q < MSG_DIM / 2; q++) {
        unsigned long long b = pack2(cB2[2 * q], cB2[2 * q + 1]);
        #pragma unroll
        for (int k = 0; k < K1_EPT; k++) acc[k][q] = b;
    }

    #pragma unroll 2
    for (int j = 0; j < HIDDEN; j++) {
        const float wa = cW1[j], wb = cW1[HIDDEN + j], bj = cB1[j];
        float h[K1_EPT];
        #pragma unroll
        for (int k = 0; k < K1_EPT; k++) {
            float u = fmaf(x[k], wa, fmaf(s[k], wb, bj));
            h[k] = tanh_fast(u);
        }
        #pragma unroll
        for (int k = 0; k < K1_EPT; k++) {
            unsigned long long hh = pack2(h[k], h[k]);
            #pragma unroll
            for (int q = 0; q < MSG_DIM / 2; q++)
                acc[k][q] = fma2(hh, cW2p[j * (MSG_DIM / 2) + q], acc[k][q]);
        }
    }

    const int rx[K1_EPT] = {ri.x, ri.y, ri.z, ri.w};
    #pragma unroll
    for (int k = 0; k < K1_EPT; k++) {
        float* p = g_hrxn + (size_t)rx[k] * MSG_DIM;
        #pragma unroll
        for (int q = 0; q < 4; q++) {
            float2 a = unpack2(acc[k][2 * q]);
            float2 b = unpack2(acc[k][2 * q + 1]);
            red_add_v4(p + 4 * q, a.x, a.y, b.x, b.y);
        }
    }
}

// ---------------------------------------------------------------------------
// Kernel 2: per-reaction rate MLP (exact tanh for precision headroom)
// ---------------------------------------------------------------------------
__global__ __launch_bounds__(256)
void rate_kernel(const float* __restrict__ W1r,
                 const float* __restrict__ b1r,
                 const float* __restrict__ W2r,
                 const float* __restrict__ b2r,
                 float* __restrict__ v_out) {
    __shared__ float sW1r[MSG_DIM * HIDDEN];
    __shared__ float sb1r[HIDDEN];
    __shared__ float sW2r[HIDDEN];
    __shared__ float sb2r;

    int t = threadIdx.x;
    for (int i = t; i < MSG_DIM * HIDDEN; i += blockDim.x) sW1r[i] = W1r[i];
    if (t < HIDDEN) { sb1r[t] = b1r[t]; sW2r[t] = W2r[t]; }
    if (t == 0) sb2r = b2r[0];
    __syncthreads();

    int r = blockIdx.x * blockDim.x + t;
    if (r >= N_RXN) return;

    float h[MSG_DIM];
    const float4* hp = reinterpret_cast<const float4*>(g_hrxn + (size_t)r * MSG_DIM);
    #pragma unroll
    for (int q = 0; q < 4; q++) {
        float4 hv = hp[q];
        h[4 * q] = hv.x; h[4 * q + 1] = hv.y; h[4 * q + 2] = hv.z; h[4 * q + 3] = hv.w;
    }

    const float C = 2.8853900817779268f;  // 2*log2(e)
    float y = sb2r;
    #pragma unroll 8
    for (int j = 0; j < HIDDEN; j++) {
        float a = sb1r[j];
        #pragma unroll
        for (int k = 0; k < MSG_DIM; k++) a = fmaf(h[k], sW1r[k * HIDDEN + j], a);
        float z = tanh_from_scaled(a * C);
        y = fmaf(z, sW2r[j], y);
    }
    float sp = fmaxf(y, 0.f) + log1pf(expf(-fabsf(y)));
    v_out[r] = sp;
}

// ---------------------------------------------------------------------------
// Kernel 3: dxdt scatter — R1/R6 winner shape; streams L2-warm from prefetch
// ---------------------------------------------------------------------------
__global__ __launch_bounds__(256)
void dxdt_kernel(const float* __restrict__ sto_all,
                 const int*   __restrict__ rxn_all,
                 const int*   __restrict__ met_all,
                 const float* __restrict__ v,
                 float* __restrict__ dxdt) {
    int i4 = blockIdx.x * blockDim.x + threadIdx.x;   // one thread = 4 edges
    if (i4 >= E_ALL / 4) return;
    float4 sv = reinterpret_cast<const float4*>(sto_all)[i4];
    int4   rv = reinterpret_cast<const int4*>(rxn_all)[i4];
    int4   mv = reinterpret_cast<const int4*>(met_all)[i4];
    red_add_f32(dxdt + mv.x, sv.x * __ldg(v + rv.x));
    red_add_f32(dxdt + mv.y, sv.y * __ldg(v + rv.y));
    red_add_f32(dxdt + mv.z, sv.z * __ldg(v + rv.z));
    red_add_f32(dxdt + mv.w, sv.w * __ldg(v + rv.w));
}

// ---------------------------------------------------------------------------
// Launch
// ---------------------------------------------------------------------------
extern "C" void kernel_launch(void* const* d_in, const int* in_sizes, int n_in,
                              void* d_out, int out_size) {
    const float* x_met   = (const float*)d_in[0];
    const float* sto_sub = (const float*)d_in[1];
    const float* sto_all = (const float*)d_in[2];
    const float* W1m     = (const float*)d_in[3];
    const float* b1m     = (const float*)d_in[4];
    const float* W2m     = (const float*)d_in[5];
    const float* b2m     = (const float*)d_in[6];
    const float* W1r     = (const float*)d_in[7];
    const float* b1r     = (const float*)d_in[8];
    const float* W2r     = (const float*)d_in[9];
    const float* b2r     = (const float*)d_in[10];
    const int*   met_sub = (const int*)d_in[11];
    const int*   rxn_sub = (const int*)d_in[12];
    const int*   met_all = (const int*)d_in[13];
    const int*   rxn_all = (const int*)d_in[14];

    float* dxdt = (float*)d_out;
    float* v    = (float*)d_out + N_MET;

    // fill constant-memory weights (device-to-device async copies: capturable)
    cudaMemcpyToSymbolAsync(cW2p, W2m, HIDDEN * MSG_DIM * sizeof(float), 0,
                            cudaMemcpyDeviceToDevice);
    cudaMemcpyToSymbolAsync(cW1,  W1m, 2 * HIDDEN * sizeof(float), 0,
                            cudaMemcpyDeviceToDevice);
    cudaMemcpyToSymbolAsync(cB1,  b1m, HIDDEN * sizeof(float), 0,
                            cudaMemcpyDeviceToDevice);
    cudaMemcpyToSymbolAsync(cB2,  b2m, MSG_DIM * sizeof(float), 0,
                            cudaMemcpyDeviceToDevice);

    // prefetch dxdt's streams into L2 first — fills overlap memsets + edge
    int pf_threads = 3 * LINES_PER_ARRAY;
    prefetch_kernel<<<(pf_threads + PF_TPB - 1) / PF_TPB, PF_TPB>>>(
        sto_all, rxn_all, met_all);

    // zero scratch + dxdt
    void* hrxn_ptr = nullptr;
    cudaGetSymbolAddress(&hrxn_ptr, g_hrxn);
    cudaMemsetAsync(hrxn_ptr, 0, N_RXN * MSG_DIM * sizeof(float));
    cudaMemsetAsync(dxdt, 0, N_MET * sizeof(float));

    int grid1 = (E_SUB / K1_EPT + K1_TPB - 1) / K1_TPB;
    edge_msg_kernel<<<grid1, K1_TPB>>>(x_met, sto_sub, met_sub, rxn_sub);

    rate_kernel<<<(N_RXN + 255) / 256, 256>>>(W1r, b1r, W2r, b2r, v);

    dxdt_kernel<<<(E_ALL / 4 + 255) / 256, 256>>>(sto_all, rxn_all, met_all, v, dxdt);
}

// round 14
// speedup vs baseline: 1.0196x; 1.0196x over previous
#include <cuda_runtime.h>
#include <cuda_bf16.h>
#include <cstdint>

// Problem constants
#define N_MET   100000
#define N_RXN   50000
#define E_SUB   2000000
#define E_ALL   4000000
#define MSG_DIM 16
#define HIDDEN  32

// Persistent scratch: per-reaction accumulated messages [N_RXN][16]
__device__ float g_hrxn[N_RXN * MSG_DIM];

// Edge-MLP weights in constant memory (filled by async D2D copies each launch).
// cW2p: W2m [32][16] row-major reinterpreted as 8 packed f32-pairs per row.
__constant__ unsigned long long cW2p[HIDDEN * (MSG_DIM / 2)];
__constant__ float cW1[2 * HIDDEN];   // row 0: x-weights, row 1: s-weights
__constant__ float cB1[HIDDEN];
__constant__ float cB2[MSG_DIM];

// ---------------------------------------------------------------------------
// helpers
// ---------------------------------------------------------------------------
__device__ __forceinline__ unsigned long long pack2(float a, float b) {
    unsigned long long r;
    asm("mov.b64 %0, {%1,%2};" : "=l"(r) : "f"(a), "f"(b));
    return r;
}
__device__ __forceinline__ unsigned long long fma2(unsigned long long a,
                                                   unsigned long long b,
                                                   unsigned long long c) {
    unsigned long long d;
    asm("fma.rn.f32x2 %0, %1, %2, %3;" : "=l"(d) : "l"(a), "l"(b), "l"(c));
    return d;
}
__device__ __forceinline__ float2 unpack2(unsigned long long a) {
    float2 f;
    asm("mov.b64 {%0,%1}, %2;" : "=f"(f.x), "=f"(f.y) : "l"(a));
    return f;
}
__device__ __forceinline__ float fast_ex2(float x) {
    float y; asm("ex2.approx.ftz.f32 %0, %1;" : "=f"(y) : "f"(x)); return y;
}
__device__ __forceinline__ float fast_rcp(float x) {
    float y; asm("rcp.approx.ftz.f32 %0, %1;" : "=f"(y) : "f"(x)); return y;
}
// single-MUFU tanh (MUFU.TANH) — edge kernel (measured: no precision impact)
__device__ __forceinline__ float tanh_fast(float x) {
    float y; asm("tanh.approx.f32 %0, %1;" : "=f"(y) : "f"(x)); return y;
}
// accurate tanh via ex2+rcp (input pre-scaled by 2*log2(e)) — rate kernel
__device__ __forceinline__ float tanh_from_scaled(float u_scaled) {
    float e = fast_ex2(u_scaled);
    float r = fast_rcp(e + 1.0f);
    return fmaf(-2.0f, r, 1.0f);
}
__device__ __forceinline__ void prefetch_l2(const void* p) {
    asm volatile("prefetch.global.L2 [%0];" :: "l"(p));
}

__device__ __forceinline__ void red_add_v4(float* p, float a, float b, float c, float d) {
    asm volatile("red.global.add.v4.f32 [%0], {%1,%2,%3,%4};"
                 :: "l"(p), "f"(a), "f"(b), "f"(c), "f"(d) : "memory");
}
__device__ __forceinline__ void red_add_f32(float* p, float a) {
    asm volatile("red.global.add.f32 [%0], %1;" :: "l"(p), "f"(a) : "memory");
}

#define LINES_PER_ARRAY (E_ALL * 4 / 128)   // 131072 lines of 128B per 16MB array

// ---------------------------------------------------------------------------
// Kernel 1: per-edge message MLP + scatter-add into g_hrxn  (R6 compute,
// measured best) + L2 prefetch of HALF the dxdt streams (sto_all, rxn_all:
// 24MB). Prefetch from a resident long-running kernel is the only variant
// that measurably warmed L2 (R12 vs R13).
// ---------------------------------------------------------------------------
#define K1_TPB 128
#define K1_EPT 4

__global__ __launch_bounds__(K1_TPB)
void edge_msg_kernel(const float* __restrict__ x_met,
                     const float* __restrict__ sto_sub,
                     const int*   __restrict__ met_sub,
                     const int*   __restrict__ rxn_sub,
                     const float* __restrict__ sto_all,
                     const int*   __restrict__ rxn_all) {
    const int tid4 = blockIdx.x * K1_TPB + threadIdx.x;   // quad index
    if (tid4 * K1_EPT >= E_SUB) return;                   // E_SUB % 4 == 0

    // ---- L2 prefetch: 1 line per thread, first 262144 threads cover
    //      sto_all + rxn_all (24MB). met_all is handled by rate_kernel. ----
    {
        int li = tid4;
        if (li < LINES_PER_ARRAY) {
            prefetch_l2(reinterpret_cast<const char*>(sto_all) + (size_t)li * 128);
        } else if (li < 2 * LINES_PER_ARRAY) {
            prefetch_l2(reinterpret_cast<const char*>(rxn_all) + (size_t)(li - LINES_PER_ARRAY) * 128);
        }
    }

    // 3 vector stream loads (LDG.128) + 4 gathers, front-batched
    int4   mi = __ldcs(reinterpret_cast<const int4*>(met_sub) + tid4);
    float4 sv = __ldcs(reinterpret_cast<const float4*>(sto_sub) + tid4);
    int4   ri = __ldcs(reinterpret_cast<const int4*>(rxn_sub) + tid4);

    float x[K1_EPT], s[K1_EPT];
    x[0] = __ldg(x_met + mi.x); x[1] = __ldg(x_met + mi.y);
    x[2] = __ldg(x_met + mi.z); x[3] = __ldg(x_met + mi.w);
    s[0] = sv.x; s[1] = sv.y; s[2] = sv.z; s[3] = sv.w;

    // accumulators init = b2m   (4 edges x 8 u64)
    unsigned long long acc[K1_EPT][MSG_DIM / 2];
    #pragma unroll
    for (int q = 0; q < MSG_DIM / 2; q++) {
        unsigned long long b = pack2(cB2[2 * q], cB2[2 * q + 1]);
        #pragma unroll
        for (int k = 0; k < K1_EPT; k++) acc[k][q] = b;
    }

    #pragma unroll 2
    for (int j = 0; j < HIDDEN; j++) {
        const float wa = cW1[j], wb = cW1[HIDDEN + j], bj = cB1[j];
        float h[K1_EPT];
        #pragma unroll
        for (int k = 0; k < K1_EPT; k++) {
            float u = fmaf(x[k], wa, fmaf(s[k], wb, bj));
            h[k] = tanh_fast(u);
        }
        #pragma unroll
        for (int k = 0; k < K1_EPT; k++) {
            unsigned long long hh = pack2(h[k], h[k]);
            #pragma unroll
            for (int q = 0; q < MSG_DIM / 2; q++)
                acc[k][q] = fma2(hh, cW2p[j * (MSG_DIM / 2) + q], acc[k][q]);
        }
    }

    const int rx[K1_EPT] = {ri.x, ri.y, ri.z, ri.w};
    #pragma unroll
    for (int k = 0; k < K1_EPT; k++) {
        float* p = g_hrxn + (size_t)rx[k] * MSG_DIM;
        #pragma unroll
        for (int q = 0; q < 4; q++) {
            float2 a = unpack2(acc[k][2 * q]);
            float2 b = unpack2(acc[k][2 * q + 1]);
            red_add_v4(p + 4 * q, a.x, a.y, b.x, b.y);
        }
    }
}

// ---------------------------------------------------------------------------
// Kernel 2: per-reaction rate MLP (exact tanh) + L2 prefetch of met_all
// (16MB, 3 lines per thread) — lands immediately before dxdt consumes it.
// ---------------------------------------------------------------------------
__global__ __launch_bounds__(256)
void rate_kernel(const float* __restrict__ W1r,
                 const float* __restrict__ b1r,
                 const float* __restrict__ W2r,
                 const float* __restrict__ b2r,
                 const int*   __restrict__ met_all,
                 float* __restrict__ v_out) {
    __shared__ float sW1r[MSG_DIM * HIDDEN];
    __shared__ float sb1r[HIDDEN];
    __shared__ float sW2r[HIDDEN];
    __shared__ float sb2r;

    int t = threadIdx.x;
    int r = blockIdx.x * blockDim.x + t;

    // prefetch met_all: thread r covers lines r, r+50000, r+100000
    #pragma unroll
    for (int c = 0; c < 3; c++) {
        int li = r + c * N_RXN;
        if (li < LINES_PER_ARRAY)
            prefetch_l2(reinterpret_cast<const char*>(met_all) + (size_t)li * 128);
    }

    for (int i = t; i < MSG_DIM * HIDDEN; i += blockDim.x) sW1r[i] = W1r[i];
    if (t < HIDDEN) { sb1r[t] = b1r[t]; sW2r[t] = W2r[t]; }
    if (t == 0) sb2r = b2r[0];
    __syncthreads();

    if (r >= N_RXN) return;

    float h[MSG_DIM];
    const float4* hp = reinterpret_cast<const float4*>(g_hrxn + (size_t)r * MSG_DIM);
    #pragma unroll
    for (int q = 0; q < 4; q++) {
        float4 hv = hp[q];
        h[4 * q] = hv.x; h[4 * q + 1] = hv.y; h[4 * q + 2] = hv.z; h[4 * q + 3] = hv.w;
    }

    const float C = 2.8853900817779268f;  // 2*log2(e)
    float y = sb2r;
    #pragma unroll 8
    for (int j = 0; j < HIDDEN; j++) {
        float a = sb1r[j];
        #pragma unroll
        for (int k = 0; k < MSG_DIM; k++) a = fmaf(h[k], sW1r[k * HIDDEN + j], a);
        float z = tanh_from_scaled(a * C);
        y = fmaf(z, sW2r[j], y);
    }
    float sp = fmaxf(y, 0.f) + log1pf(expf(-fabsf(y)));
    v_out[r] = sp;
}

// ---------------------------------------------------------------------------
// Kernel 3: dxdt scatter — R1/R6 winner shape; streams L2-warm
// ---------------------------------------------------------------------------
__global__ __launch_bounds__(256)
void dxdt_kernel(const float* __restrict__ sto_all,
                 const int*   __restrict__ rxn_all,
                 const int*   __restrict__ met_all,
                 const float* __restrict__ v,
                 float* __restrict__ dxdt) {
    int i4 = blockIdx.x * blockDim.x + threadIdx.x;   // one thread = 4 edges
    if (i4 >= E_ALL / 4) return;
    float4 sv = reinterpret_cast<const float4*>(sto_all)[i4];
    int4   rv = reinterpret_cast<const int4*>(rxn_all)[i4];
    int4   mv = reinterpret_cast<const int4*>(met_all)[i4];
    red_add_f32(dxdt + mv.x, sv.x * __ldg(v + rv.x));
    red_add_f32(dxdt + mv.y, sv.y * __ldg(v + rv.y));
    red_add_f32(dxdt + mv.z, sv.z * __ldg(v + rv.z));
    red_add_f32(dxdt + mv.w, sv.w * __ldg(v + rv.w));
}

// ---------------------------------------------------------------------------
// Launch
// ---------------------------------------------------------------------------
extern "C" void kernel_launch(void* const* d_in, const int* in_sizes, int n_in,
                              void* d_out, int out_size) {
    const float* x_met   = (const float*)d_in[0];
    const float* sto_sub = (const float*)d_in[1];
    const float* sto_all = (const float*)d_in[2];
    const float* W1m     = (const float*)d_in[3];
    const float* b1m     = (const float*)d_in[4];
    const float* W2m     = (const float*)d_in[5];
    const float* b2m     = (const float*)d_in[6];
    const float* W1r     = (const float*)d_in[7];
    const float* b1r     = (const float*)d_in[8];
    const float* W2r     = (const float*)d_in[9];
    const float* b2r     = (const float*)d_in[10];
    const int*   met_sub = (const int*)d_in[11];
    const int*   rxn_sub = (const int*)d_in[12];
    const int*   met_all = (const int*)d_in[13];
    const int*   rxn_all = (const int*)d_in[14];

    float* dxdt = (float*)d_out;
    float* v    = (float*)d_out + N_MET;

    // fill constant-memory weights (device-to-device async copies: capturable)
    cudaMemcpyToSymbolAsync(cW2p, W2m, HIDDEN * MSG_DIM * sizeof(float), 0,
                            cudaMemcpyDeviceToDevice);
    cudaMemcpyToSymbolAsync(cW1,  W1m, 2 * HIDDEN * sizeof(float), 0,
                            cudaMemcpyDeviceToDevice);
    cudaMemcpyToSymbolAsync(cB1,  b1m, HIDDEN * sizeof(float), 0,
                            cudaMemcpyDeviceToDevice);
    cudaMemcpyToSymbolAsync(cB2,  b2m, MSG_DIM * sizeof(float), 0,
                            cudaMemcpyDeviceToDevice);

    // zero scratch + dxdt
    void* hrxn_ptr = nullptr;
    cudaGetSymbolAddress(&hrxn_ptr, g_hrxn);
    cudaMemsetAsync(hrxn_ptr, 0, N_RXN * MSG_DIM * sizeof(float));
    cudaMemsetAsync(dxdt, 0, N_MET * sizeof(float));

    int grid1 = (E_SUB / K1_EPT + K1_TPB - 1) / K1_TPB;
    edge_msg_kernel<<<grid1, K1_TPB>>>(x_met, sto_sub, met_sub, rxn_sub,
                                       sto_all, rxn_all);

    rate_kernel<<<(N_RXN + 255) / 256, 256>>>(W1r, b1r, W2r, b2r, met_all, v);

    dxdt_kernel<<<(E_ALL / 4 + 255) / 256, 256>>>(sto_all, rxn_all, met_all, v, dxdt);
}